// round 12
// baseline (speedup 1.0000x reference)
#include <cuda_runtime.h>
#include <cuda_fp16.h>
#include <math.h>
#include <stdint.h>

#define NN 51200      // nodes
#define NE 819200     // edges
#define HD 128        // hidden / in dim
#define NG 128        // graphs
#define SEG 400       // nodes per graph
#define OUTC 10
#define NT  (NN / 128)          // 400 M-tiles

// ---------------- scratch (device globals) ---------------------------------
__device__ float g_y[NN * HD];     // conv output (post-relu)
__device__ __align__(16) __half g_xh[NN * HD];   // fp16 hi of x (also gather src)
__device__ __align__(16) __half g_xl[NN * HD];   // fp16 residual of x
__device__ __align__(16) __half g_ah[NN * HD];   // fp16 hi of agg
__device__ __align__(16) __half g_al[NN * HD];   // fp16 residual of agg
__device__ __align__(16) __half g_w[4 * HD * HD]; // weight hi images [n][k]
__device__ int   g_src[NE];
__device__ int   g_dst[NE];
__device__ int   g_p1[NN];
__device__ int   g_p2[NN];
__device__ int   g_cnt[NN];        // zero at load; scan1 re-zeroes each pass
__device__ int   g_scanL[NN];
__device__ int   g_bsum[256];
__device__ int   g_rowstart[NN + 1];
__device__ int   g_cursor[NN];
__device__ int   g_eidx[NE];

// ---------------- helpers ---------------------------------------------------
__device__ __forceinline__ uint32_t smem_to_u32(const void* p) {
    uint32_t a;
    asm("{ .reg .u64 t; cvta.to.shared.u64 t, %1; cvt.u32.u64 %0, t; }"
        : "=r"(a) : "l"(p));
    return a;
}
#define CP_ASYNC16(dst, src) \
    asm volatile("cp.async.cg.shared.global [%0], [%1], 16;" \
                 :: "r"(dst), "l"(src) : "memory")
#define CP_COMMIT() asm volatile("cp.async.commit_group;" ::: "memory")
#define CP_WAIT2()  asm volatile("cp.async.wait_group 2;" ::: "memory")

__device__ __forceinline__ void ldsm_x4(uint32_t* r, uint32_t addr) {
    asm volatile("ldmatrix.sync.aligned.m8n8.x4.shared.b16 {%0,%1,%2,%3}, [%4];"
                 : "=r"(r[0]), "=r"(r[1]), "=r"(r[2]), "=r"(r[3]) : "r"(addr));
}
__device__ __forceinline__ void mma16816(float* c, const uint32_t* a, const uint32_t* b) {
    asm volatile("mma.sync.aligned.m16n8k16.row.col.f32.f16.f16.f32 "
                 "{%0,%1,%2,%3},{%4,%5,%6,%7},{%8,%9},{%0,%1,%2,%3};"
                 : "+f"(c[0]), "+f"(c[1]), "+f"(c[2]), "+f"(c[3])
                 : "r"(a[0]), "r"(a[1]), "r"(a[2]), "r"(a[3]), "r"(b[0]), "r"(b[1]));
}

__device__ __forceinline__ uint32_t pack2(__half a, __half b) {
    return (uint32_t)__half_as_ushort(a) | ((uint32_t)__half_as_ushort(b) << 16);
}

// fp16 hi/residual split: hi + lo == v to ~2^-22 relative
__device__ __forceinline__ void write_hilo(__half* hi, __half* lo,
                                           int node, int lane, float4 v) {
    int off = node * HD + lane * 4;
    __half hx = __float2half_rn(v.x), hy = __float2half_rn(v.y);
    __half hz = __float2half_rn(v.z), hw = __float2half_rn(v.w);
    uint2 ph, pl;
    ph.x = pack2(hx, hy);
    ph.y = pack2(hz, hw);
    pl.x = pack2(__float2half_rn(v.x - __half2float(hx)),
                 __float2half_rn(v.y - __half2float(hy)));
    pl.y = pack2(__float2half_rn(v.z - __half2float(hz)),
                 __float2half_rn(v.w - __half2float(hw)));
    *(uint2*)&hi[off] = ph;
    *(uint2*)&lo[off] = pl;
}

// ---------------- convert + histogram (+ inline dtype detect) ---------------
__global__ void convhist_kernel(const void* __restrict__ eraw,
                                const void* __restrict__ p1raw,
                                const void* __restrict__ p2raw) {
    __shared__ int s_is64;
    int tid = threadIdx.x;
    if (tid == 0) {
        // int64 data: high words of first 8 entries all zero (values < 2^32).
        // int32 data: those words are random dst indices; P(all zero) ~ 5e-38.
        const unsigned* e = (const unsigned*)eraw;
        int all0 = 1;
        #pragma unroll 1
        for (int k = 0; k < 8; k++)
            if (e[2 * k + 1] != 0u) { all0 = 0; break; }
        s_is64 = all0;
    }
    __syncthreads();
    const bool is64 = (s_is64 != 0);
    int i = blockIdx.x * blockDim.x + tid;
    if (i < NE) {
        int s = is64 ? (int)((const long long*)eraw)[i] : ((const int*)eraw)[i];
        int d = is64 ? (int)((const long long*)eraw)[NE + i] : ((const int*)eraw)[NE + i];
        g_src[i] = s;
        g_dst[i] = d;
        atomicAdd(&g_cnt[d], 1);
    }
    if (i < NN) {
        g_p1[i] = is64 ? (int)((const long long*)p1raw)[i] : ((const int*)p1raw)[i];
        g_p2[i] = is64 ? (int)((const long long*)p2raw)[i] : ((const int*)p2raw)[i];
    }
}

// ---------------- scan chain: scan1 (+cnt clear), scan23 --------------------
__global__ void scan1_kernel() {
    __shared__ int sh[256];
    int b = blockIdx.x, t = threadIdx.x;
    int i = b * 256 + t;
    int v = (i < NN) ? g_cnt[i] : 0;
    if (i < NN) g_cnt[i] = 0;        // self-clean for next replay
    sh[t] = v;
    __syncthreads();
    #pragma unroll
    for (int off = 1; off < 256; off <<= 1) {
        int add = (t >= off) ? sh[t - off] : 0;
        __syncthreads();
        sh[t] += add;
        __syncthreads();
    }
    if (i < NN) g_scanL[i] = sh[t] - v;
    if (t == 255) g_bsum[b] = sh[255];
}

// per-block re-derivation of the 200-entry block-sum prefix (replaces scan2)
__global__ void scan23_kernel() {
    __shared__ int sh[256];
    int b = blockIdx.x, t = threadIdx.x;
    int v = (t < NN / 256) ? g_bsum[t] : 0;
    sh[t] = v;
    __syncthreads();
    #pragma unroll
    for (int off = 1; off < 256; off <<= 1) {
        int add = (t >= off) ? sh[t - off] : 0;
        __syncthreads();
        sh[t] += add;
        __syncthreads();
    }
    int boff = (b == 0) ? 0 : sh[b - 1];   // exclusive prefix for this block
    int i = b * 256 + t;
    if (i < NN) {
        int rs = g_scanL[i] + boff;
        g_rowstart[i] = rs;
        g_cursor[i] = rs;
    }
    if (b == 0 && t == 0) g_rowstart[NN] = NE;
}

__global__ void scatter_kernel() {
    int e = blockIdx.x * blockDim.x + threadIdx.x;
    if (e < NE) {
        int pos = atomicAdd(&g_cursor[g_dst[e]], 1);
        g_eidx[pos] = g_src[e];
    }
}

// ---------------- merged prep: x0 fp16 split + weight images ---------------
// blocks [0, 6400): xprep (8 nodes/block); blocks [6400, 6404): wprep
__global__ void prep_kernel(const float* __restrict__ xin,
                            const float* __restrict__ W0r,
                            const float* __restrict__ W0e,
                            const float* __restrict__ W1r,
                            const float* __restrict__ W1e) {
    if (blockIdx.x < NN / 8) {
        int warp = (blockIdx.x * blockDim.x + threadIdx.x) >> 5;
        int lane = threadIdx.x & 31;
        float4 v = *(const float4*)&xin[(size_t)warp * HD + lane * 4];
        write_hilo(g_xh, g_xl, warp, lane, v);
    } else {
        if (threadIdx.x >= 128) return;
        int m = blockIdx.x - NN / 8;
        const float* Ws[4] = {W0r, W0e, W1r, W1e};
        const float* W = Ws[m];
        __half* hi = g_w + (size_t)m * HD * HD;
        int n = threadIdx.x;
        for (int k0 = 0; k0 < HD; k0 += 4) {
            uint2 p;
            p.x = pack2(__float2half_rn(W[(k0 + 0) * HD + n]),
                        __float2half_rn(W[(k0 + 1) * HD + n]));
            p.y = pack2(__float2half_rn(W[(k0 + 2) * HD + n]),
                        __float2half_rn(W[(k0 + 3) * HD + n]));
            *(uint2*)&hi[n * HD + k0] = p;
        }
    }
}

// ---------------- aggregation: warp/node, unroll-2, fp16 gather ------------
__global__ void agg_kernel() {
    int warp = (blockIdx.x * blockDim.x + threadIdx.x) >> 5;
    if (warp >= NN) return;
    int lane = threadIdx.x & 31;
    int s = g_rowstart[warp];
    int e = g_rowstart[warp + 1];
    float4 acc = make_float4(0.f, 0.f, 0.f, 0.f);
    int j = s;
    for (; j + 1 < e; j += 2) {
        int u0 = g_eidx[j], u1 = g_eidx[j + 1];
        uint2 p0 = *(const uint2*)&g_xh[u0 * HD + lane * 4];
        uint2 p1 = *(const uint2*)&g_xh[u1 * HD + lane * 4];
        float2 a0 = __half22float2(*(const __half2*)&p0.x);
        float2 b0 = __half22float2(*(const __half2*)&p0.y);
        float2 a1 = __half22float2(*(const __half2*)&p1.x);
        float2 b1 = __half22float2(*(const __half2*)&p1.y);
        acc.x += a0.x + a1.x; acc.y += a0.y + a1.y;
        acc.z += b0.x + b1.x; acc.w += b0.y + b1.y;
    }
    if (j < e) {
        int u = g_eidx[j];
        uint2 p = *(const uint2*)&g_xh[u * HD + lane * 4];
        float2 a = __half22float2(*(const __half2*)&p.x);
        float2 b = __half22float2(*(const __half2*)&p.y);
        acc.x += a.x; acc.y += a.y; acc.z += b.x; acc.w += b.y;
    }
    write_hilo(g_ah, g_al, warp, lane, acc);
}

// ---------------- HMMA GEMM: 4 fp16 segments (K=512 effective) -------------
__global__ void __launch_bounds__(256, 2)
gemm_kernel(const __half* __restrict__ xh, const __half* __restrict__ xl,
            const __half* __restrict__ ah, const __half* __restrict__ al,
            const __half* __restrict__ wr, const __half* __restrict__ we,
            const float* __restrict__ bias, float* __restrict__ yout) {
    extern __shared__ char smem[];
    __shared__ const uint4* Atab[4];
    __shared__ const uint4* Btab[4];
    const int tid = threadIdx.x, lane = tid & 31, wid = tid >> 5;
    const int wm = wid >> 1, wn = wid & 1;
    const int tile = blockIdx.x;

    if (tid == 0) {
        size_t toff = (size_t)tile * 128 * HD;
        Atab[0] = (const uint4*)(xh + toff); Atab[1] = (const uint4*)(ah + toff);
        Atab[2] = (const uint4*)(xl + toff); Atab[3] = (const uint4*)(al + toff);
        Btab[0] = (const uint4*)wr; Btab[1] = (const uint4*)we;
        Btab[2] = (const uint4*)wr; Btab[3] = (const uint4*)we;
    }
    __syncthreads();
    const uint32_t sbase = smem_to_u32(smem);

    auto prefetch = [&](int cc, int st) {
        int seg = cc >> 1, ko4 = (cc & 1) << 3;
        const uint4* As = Atab[seg];
        const uint4* Bs = Btab[seg];
        uint32_t sA = sbase + st * 32768;
        uint32_t sB = sA + 16384;
        #pragma unroll
        for (int i = 0; i < 4; i++) {
            int idx = tid + 256 * i;
            int row = idx >> 3, c4 = idx & 7;
            int sw = (row * 8 + (c4 ^ (row & 7))) * 16;
            CP_ASYNC16(sA + sw, As + row * 16 + ko4 + c4);
            CP_ASYNC16(sB + sw, Bs + row * 16 + ko4 + c4);
        }
    };

    prefetch(0, 0); CP_COMMIT();
    prefetch(1, 1); CP_COMMIT();
    prefetch(2, 2); CP_COMMIT();

    float acc[2][8][4] = {};
    int st = 0;
    #pragma unroll 1
    for (int c = 0; c < 8; c++) {
        CP_WAIT2();
        __syncthreads();
        uint32_t sA = sbase + st * 32768;
        uint32_t sB = sA + 16384;
        #pragma unroll
        for (int kk = 0; kk < 4; kk++) {
            uint32_t a0[4], a1[4];
            {
                int row = wm * 32 + (lane & 15);
                int c4 = kk * 2 + (lane >> 4);
                ldsm_x4(a0, sA + (row * 8 + (c4 ^ (row & 7))) * 16);
                int row1 = row + 16;
                ldsm_x4(a1, sA + (row1 * 8 + (c4 ^ (row1 & 7))) * 16);
            }
            uint32_t b[4][4];
            #pragma unroll
            for (int p = 0; p < 4; p++) {
                int nrow = wn * 64 + p * 16 + ((lane >> 4) << 3) + (lane & 7);
                int c4 = kk * 2 + ((lane >> 3) & 1);
                ldsm_x4(b[p], sB + (nrow * 8 + (c4 ^ (nrow & 7))) * 16);
            }
            #pragma unroll
            for (int nt = 0; nt < 8; nt++) {
                mma16816(acc[0][nt], a0, &b[nt >> 1][(nt & 1) * 2]);
                mma16816(acc[1][nt], a1, &b[nt >> 1][(nt & 1) * 2]);
            }
        }
        __syncthreads();
        if (c + 3 < 8) prefetch(c + 3, st);
        CP_COMMIT();
        st = (st == 2) ? 0 : st + 1;
    }

    int r0 = tile * 128 + wm * 32 + (lane >> 2);
    int cb = wn * 64 + (lane & 3) * 2;
    #pragma unroll
    for (int mt = 0; mt < 2; mt++) {
        #pragma unroll
        for (int nt = 0; nt < 8; nt++) {
            int col = cb + nt * 8;
            int row = r0 + mt * 16;
            float bx = bias[col], by = bias[col + 1];
            float2 v;
            v.x = fmaxf(acc[mt][nt][0] + bx, 0.f);
            v.y = fmaxf(acc[mt][nt][1] + by, 0.f);
            *(float2*)&yout[(size_t)row * HD + col] = v;
            v.x = fmaxf(acc[mt][nt][2] + bx, 0.f);
            v.y = fmaxf(acc[mt][nt][3] + by, 0.f);
            *(float2*)&yout[(size_t)(row + 8) * HD + col] = v;
        }
    }
}

// ---------------- mixup: writes fp16 hi/lo of new x ------------------------
__global__ void mixup_kernel(const float* __restrict__ lam, int which,
                             const float* __restrict__ yin) {
    int warp = (blockIdx.x * blockDim.x + threadIdx.x) >> 5;
    if (warp >= NN) return;
    int lane = threadIdx.x & 31;
    const int* perm = which ? g_p2 : g_p1;
    int p = perm[warp];
    float l = lam[0];
    float4 a = *(const float4*)&yin[(size_t)warp * HD + lane * 4];
    float4 b = *(const float4*)&yin[(size_t)p * HD + lane * 4];
    float4 o;
    o.x = l * a.x + (1.f - l) * b.x;
    o.y = l * a.y + (1.f - l) * b.y;
    o.z = l * a.z + (1.f - l) * b.z;
    o.w = l * a.w + (1.f - l) * b.w;
    write_hilo(g_xh, g_xl, warp, lane, o);
}

// ---------------- fused pool + head (segment-local; mixup3 no-op) ----------
__global__ void poolhead_kernel(const float* __restrict__ yin,
                                const float* __restrict__ Wl,
                                const float* __restrict__ bl,
                                float* __restrict__ out) {
    __shared__ float ps[256];
    int g = blockIdx.x, t = threadIdx.x;
    int col = t & 127, half = t >> 7;
    float acc = 0.f;
    int base = g * SEG + half * 200;
    #pragma unroll 4
    for (int r = 0; r < 200; r++)
        acc += yin[(size_t)(base + r) * HD + col];
    ps[t] = acc;
    __syncthreads();
    if (t < 128) ps[t] += ps[t + 128];
    __syncthreads();
    if (t < 32) {
        float pv[4];
        #pragma unroll
        for (int q = 0; q < 4; q++) pv[q] = ps[t + q * 32];
        float logits[OUTC];
        #pragma unroll
        for (int o = 0; o < OUTC; o++) {
            float s = 0.f;
            #pragma unroll
            for (int q = 0; q < 4; q++)
                s += pv[q] * Wl[(t + q * 32) * OUTC + o];
            #pragma unroll
            for (int off = 16; off; off >>= 1)
                s += __shfl_down_sync(0xffffffffu, s, off);
            logits[o] = s;
        }
        if (t == 0) {
            float m = -1e30f;
            #pragma unroll
            for (int o = 0; o < OUTC; o++) {
                logits[o] += bl[o];
                m = fmaxf(m, logits[o]);
            }
            float se = 0.f;
            #pragma unroll
            for (int o = 0; o < OUTC; o++) se += expf(logits[o] - m);
            float lse = m + logf(se);
            #pragma unroll
            for (int o = 0; o < OUTC; o++) out[g * OUTC + o] = logits[o] - lse;
        }
    }
}

// ---------------- launch ----------------------------------------------------
extern "C" void kernel_launch(void* const* d_in, const int* in_sizes, int n_in,
                              void* d_out, int out_size) {
    const float* x0      = (const float*)d_in[0];
    const void*  eidx    = d_in[1];
    const float* lam     = (const float*)d_in[2];
    const void*  perm1   = d_in[5];
    const void*  perm2   = d_in[6];
    const float* W1_rel  = (const float*)d_in[8];
    const float* b1_rel  = (const float*)d_in[9];
    const float* W1_root = (const float*)d_in[10];
    const float* W2_rel  = (const float*)d_in[11];
    const float* b2_rel  = (const float*)d_in[12];
    const float* W2_root = (const float*)d_in[13];
    const float* W_lin   = (const float*)d_in[14];
    const float* b_lin   = (const float*)d_in[15];
    float* out = (float*)d_out;

    const int GEMM_SMEM = 3 * 32768;
    static int smem_set = 0;
    if (!smem_set) {
        cudaFuncSetAttribute(gemm_kernel,
                             cudaFuncAttributeMaxDynamicSharedMemorySize, GEMM_SMEM);
        smem_set = 1;
    }

    convhist_kernel<<<(NE + 255) / 256, 256>>>(eidx, perm1, perm2);
    scan1_kernel<<<(NN + 255) / 256, 256>>>();
    scan23_kernel<<<(NN + 255) / 256, 256>>>();
    scatter_kernel<<<(NE + 255) / 256, 256>>>();
    prep_kernel<<<NN / 8 + 4, 256>>>(x0, W1_root, W1_rel, W2_root, W2_rel);

    __half *xh, *xl, *ah, *al, *w;
    float *gy;
    cudaGetSymbolAddress((void**)&xh, g_xh);
    cudaGetSymbolAddress((void**)&xl, g_xl);
    cudaGetSymbolAddress((void**)&ah, g_ah);
    cudaGetSymbolAddress((void**)&al, g_al);
    cudaGetSymbolAddress((void**)&w,  g_w);
    cudaGetSymbolAddress((void**)&gy, g_y);
    __half* w0r = w + 0 * HD * HD;
    __half* w0e = w + 1 * HD * HD;
    __half* w1r = w + 2 * HD * HD;
    __half* w1e = w + 3 * HD * HD;

    // Layer 1
    agg_kernel<<<(NN * 32 + 255) / 256, 256>>>();
    gemm_kernel<<<NT, 256, GEMM_SMEM>>>(xh, xl, ah, al, w0r, w0e, b1_rel, gy);
    mixup_kernel<<<(NN * 32 + 255) / 256, 256>>>(lam, 0, gy);

    // Layer 2
    agg_kernel<<<(NN * 32 + 255) / 256, 256>>>();
    gemm_kernel<<<NT, 256, GEMM_SMEM>>>(xh, xl, ah, al, w1r, w1e, b2_rel, gy);
    mixup_kernel<<<(NN * 32 + 255) / 256, 256>>>(lam, 1, gy);

    // Layer 3 (conv2 weights reused; mixup3 invariant under pooling)
    agg_kernel<<<(NN * 32 + 255) / 256, 256>>>();
    gemm_kernel<<<NT, 256, GEMM_SMEM>>>(xh, xl, ah, al, w1r, w1e, b2_rel, gy);

    poolhead_kernel<<<NG, 256>>>(gy, W_lin, b_lin, out);
}

// round 13
// speedup vs baseline: 1.0159x; 1.0159x over previous
#include <cuda_runtime.h>
#include <cuda_fp16.h>
#include <math.h>
#include <stdint.h>

#define NN 51200      // nodes
#define NE 819200     // edges
#define HD 128        // hidden / in dim
#define NG 128        // graphs
#define SEG 400       // nodes per graph
#define OUTC 10
#define NT  (NN / 128)          // 400 M-tiles

// ---------------- scratch (device globals) ---------------------------------
__device__ __align__(16) __half g_y[NN * HD];    // conv output (post-relu), fp16
__device__ __align__(16) __half g_xh[NN * HD];   // fp16 hi of x (also gather src)
__device__ __align__(16) __half g_xl[NN * HD];   // fp16 residual of x
__device__ __align__(16) __half g_ah[NN * HD];   // fp16 hi of agg
__device__ __align__(16) __half g_al[NN * HD];   // fp16 residual of agg
__device__ __align__(16) __half g_w[4 * HD * HD]; // weight hi images [n][k]
__device__ int   g_src[NE];
__device__ int   g_dst[NE];
__device__ int   g_rank[NE];       // within-dst-bucket rank (from hist atomic)
__device__ int   g_p1[NN];
__device__ int   g_p2[NN];
__device__ int   g_cnt[NN];        // zero at load; scan1 re-zeroes each pass
__device__ int   g_scanL[NN];
__device__ int   g_bsum[256];
__device__ int   g_rowstart[NN + 1];
__device__ int   g_eidx[NE];

// ---------------- helpers ---------------------------------------------------
__device__ __forceinline__ uint32_t smem_to_u32(const void* p) {
    uint32_t a;
    asm("{ .reg .u64 t; cvta.to.shared.u64 t, %1; cvt.u32.u64 %0, t; }"
        : "=r"(a) : "l"(p));
    return a;
}
#define CP_ASYNC16(dst, src) \
    asm volatile("cp.async.cg.shared.global [%0], [%1], 16;" \
                 :: "r"(dst), "l"(src) : "memory")
#define CP_COMMIT() asm volatile("cp.async.commit_group;" ::: "memory")
#define CP_WAIT2()  asm volatile("cp.async.wait_group 2;" ::: "memory")

__device__ __forceinline__ void ldsm_x4(uint32_t* r, uint32_t addr) {
    asm volatile("ldmatrix.sync.aligned.m8n8.x4.shared.b16 {%0,%1,%2,%3}, [%4];"
                 : "=r"(r[0]), "=r"(r[1]), "=r"(r[2]), "=r"(r[3]) : "r"(addr));
}
__device__ __forceinline__ void mma16816(float* c, const uint32_t* a, const uint32_t* b) {
    asm volatile("mma.sync.aligned.m16n8k16.row.col.f32.f16.f16.f32 "
                 "{%0,%1,%2,%3},{%4,%5,%6,%7},{%8,%9},{%0,%1,%2,%3};"
                 : "+f"(c[0]), "+f"(c[1]), "+f"(c[2]), "+f"(c[3])
                 : "r"(a[0]), "r"(a[1]), "r"(a[2]), "r"(a[3]), "r"(b[0]), "r"(b[1]));
}

__device__ __forceinline__ uint32_t pack2(__half a, __half b) {
    return (uint32_t)__half_as_ushort(a) | ((uint32_t)__half_as_ushort(b) << 16);
}

// fp16 hi/residual split: hi + lo == v to ~2^-22 relative
__device__ __forceinline__ void write_hilo(__half* hi, __half* lo,
                                           int node, int lane, float4 v) {
    int off = node * HD + lane * 4;
    __half hx = __float2half_rn(v.x), hy = __float2half_rn(v.y);
    __half hz = __float2half_rn(v.z), hw = __float2half_rn(v.w);
    uint2 ph, pl;
    ph.x = pack2(hx, hy);
    ph.y = pack2(hz, hw);
    pl.x = pack2(__float2half_rn(v.x - __half2float(hx)),
                 __float2half_rn(v.y - __half2float(hy)));
    pl.y = pack2(__float2half_rn(v.z - __half2float(hz)),
                 __float2half_rn(v.w - __half2float(hw)));
    *(uint2*)&hi[off] = ph;
    *(uint2*)&lo[off] = pl;
}

// ---------------- convert + histogram + rank (+ inline dtype detect) --------
__global__ void convhist_kernel(const void* __restrict__ eraw,
                                const void* __restrict__ p1raw,
                                const void* __restrict__ p2raw) {
    __shared__ int s_is64;
    int tid = threadIdx.x;
    if (tid == 0) {
        const unsigned* e = (const unsigned*)eraw;
        int all0 = 1;
        #pragma unroll 1
        for (int k = 0; k < 8; k++)
            if (e[2 * k + 1] != 0u) { all0 = 0; break; }
        s_is64 = all0;
    }
    __syncthreads();
    const bool is64 = (s_is64 != 0);
    int i = blockIdx.x * blockDim.x + tid;
    if (i < NE) {
        int s = is64 ? (int)((const long long*)eraw)[i] : ((const int*)eraw)[i];
        int d = is64 ? (int)((const long long*)eraw)[NE + i] : ((const int*)eraw)[NE + i];
        g_src[i] = s;
        g_dst[i] = d;
        g_rank[i] = atomicAdd(&g_cnt[d], 1);
    }
    if (i < NN) {
        g_p1[i] = is64 ? (int)((const long long*)p1raw)[i] : ((const int*)p1raw)[i];
        g_p2[i] = is64 ? (int)((const long long*)p2raw)[i] : ((const int*)p2raw)[i];
    }
}

// ---------------- scan chain: scan1 (+cnt clear), scan23 --------------------
__global__ void scan1_kernel() {
    __shared__ int sh[256];
    int b = blockIdx.x, t = threadIdx.x;
    int i = b * 256 + t;
    int v = (i < NN) ? g_cnt[i] : 0;
    if (i < NN) g_cnt[i] = 0;        // self-clean for next replay
    sh[t] = v;
    __syncthreads();
    #pragma unroll
    for (int off = 1; off < 256; off <<= 1) {
        int add = (t >= off) ? sh[t - off] : 0;
        __syncthreads();
        sh[t] += add;
        __syncthreads();
    }
    if (i < NN) g_scanL[i] = sh[t] - v;
    if (t == 255) g_bsum[b] = sh[255];
}

// per-block re-derivation of the 200-entry block-sum prefix (replaces scan2)
__global__ void scan23_kernel() {
    __shared__ int sh[256];
    int b = blockIdx.x, t = threadIdx.x;
    int v = (t < NN / 256) ? g_bsum[t] : 0;
    sh[t] = v;
    __syncthreads();
    #pragma unroll
    for (int off = 1; off < 256; off <<= 1) {
        int add = (t >= off) ? sh[t - off] : 0;
        __syncthreads();
        sh[t] += add;
        __syncthreads();
    }
    int boff = (b == 0) ? 0 : sh[b - 1];   // exclusive prefix for this block
    int i = b * 256 + t;
    if (i < NN) g_rowstart[i] = g_scanL[i] + boff;
    if (b == 0 && t == 0) g_rowstart[NN] = NE;
}

// atomic-free scatter: position = rowstart[dst] + rank (captured in convhist)
__global__ void scatter_kernel() {
    int e = blockIdx.x * blockDim.x + threadIdx.x;
    if (e < NE) {
        int pos = g_rowstart[g_dst[e]] + g_rank[e];
        g_eidx[pos] = g_src[e];
    }
}

// ---------------- merged prep: x0 fp16 split + weight images ---------------
__global__ void prep_kernel(const float* __restrict__ xin,
                            const float* __restrict__ W0r,
                            const float* __restrict__ W0e,
                            const float* __restrict__ W1r,
                            const float* __restrict__ W1e) {
    if (blockIdx.x < NN / 8) {
        int warp = (blockIdx.x * blockDim.x + threadIdx.x) >> 5;
        int lane = threadIdx.x & 31;
        float4 v = *(const float4*)&xin[(size_t)warp * HD + lane * 4];
        write_hilo(g_xh, g_xl, warp, lane, v);
    } else {
        if (threadIdx.x >= 128) return;
        int m = blockIdx.x - NN / 8;
        const float* Ws[4] = {W0r, W0e, W1r, W1e};
        const float* W = Ws[m];
        __half* hi = g_w + (size_t)m * HD * HD;
        int n = threadIdx.x;
        for (int k0 = 0; k0 < HD; k0 += 4) {
            uint2 p;
            p.x = pack2(__float2half_rn(W[(k0 + 0) * HD + n]),
                        __float2half_rn(W[(k0 + 1) * HD + n]));
            p.y = pack2(__float2half_rn(W[(k0 + 2) * HD + n]),
                        __float2half_rn(W[(k0 + 3) * HD + n]));
            *(uint2*)&hi[n * HD + k0] = p;
        }
    }
}

// ---------------- aggregation: warp/node, unroll-2, fp16 gather ------------
__global__ void agg_kernel() {
    int warp = (blockIdx.x * blockDim.x + threadIdx.x) >> 5;
    if (warp >= NN) return;
    int lane = threadIdx.x & 31;
    int s = g_rowstart[warp];
    int e = g_rowstart[warp + 1];
    float4 acc = make_float4(0.f, 0.f, 0.f, 0.f);
    int j = s;
    for (; j + 1 < e; j += 2) {
        int u0 = g_eidx[j], u1 = g_eidx[j + 1];
        uint2 p0 = *(const uint2*)&g_xh[u0 * HD + lane * 4];
        uint2 p1 = *(const uint2*)&g_xh[u1 * HD + lane * 4];
        float2 a0 = __half22float2(*(const __half2*)&p0.x);
        float2 b0 = __half22float2(*(const __half2*)&p0.y);
        float2 a1 = __half22float2(*(const __half2*)&p1.x);
        float2 b1 = __half22float2(*(const __half2*)&p1.y);
        acc.x += a0.x + a1.x; acc.y += a0.y + a1.y;
        acc.z += b0.x + b1.x; acc.w += b0.y + b1.y;
    }
    if (j < e) {
        int u = g_eidx[j];
        uint2 p = *(const uint2*)&g_xh[u * HD + lane * 4];
        float2 a = __half22float2(*(const __half2*)&p.x);
        float2 b = __half22float2(*(const __half2*)&p.y);
        acc.x += a.x; acc.y += a.y; acc.z += b.x; acc.w += b.y;
    }
    write_hilo(g_ah, g_al, warp, lane, acc);
}

// ---------------- HMMA GEMM: 4 fp16 segments, fp16 y output ----------------
__global__ void __launch_bounds__(256, 2)
gemm_kernel(const __half* __restrict__ xh, const __half* __restrict__ xl,
            const __half* __restrict__ ah, const __half* __restrict__ al,
            const __half* __restrict__ wr, const __half* __restrict__ we,
            const float* __restrict__ bias, __half* __restrict__ yout) {
    extern __shared__ char smem[];
    __shared__ const uint4* Atab[4];
    __shared__ const uint4* Btab[4];
    const int tid = threadIdx.x, lane = tid & 31, wid = tid >> 5;
    const int wm = wid >> 1, wn = wid & 1;
    const int tile = blockIdx.x;

    if (tid == 0) {
        size_t toff = (size_t)tile * 128 * HD;
        Atab[0] = (const uint4*)(xh + toff); Atab[1] = (const uint4*)(ah + toff);
        Atab[2] = (const uint4*)(xl + toff); Atab[3] = (const uint4*)(al + toff);
        Btab[0] = (const uint4*)wr; Btab[1] = (const uint4*)we;
        Btab[2] = (const uint4*)wr; Btab[3] = (const uint4*)we;
    }
    __syncthreads();
    const uint32_t sbase = smem_to_u32(smem);

    auto prefetch = [&](int cc, int st) {
        int seg = cc >> 1, ko4 = (cc & 1) << 3;
        const uint4* As = Atab[seg];
        const uint4* Bs = Btab[seg];
        uint32_t sA = sbase + st * 32768;
        uint32_t sB = sA + 16384;
        #pragma unroll
        for (int i = 0; i < 4; i++) {
            int idx = tid + 256 * i;
            int row = idx >> 3, c4 = idx & 7;
            int sw = (row * 8 + (c4 ^ (row & 7))) * 16;
            CP_ASYNC16(sA + sw, As + row * 16 + ko4 + c4);
            CP_ASYNC16(sB + sw, Bs + row * 16 + ko4 + c4);
        }
    };

    prefetch(0, 0); CP_COMMIT();
    prefetch(1, 1); CP_COMMIT();
    prefetch(2, 2); CP_COMMIT();

    float acc[2][8][4] = {};
    int st = 0;
    #pragma unroll 1
    for (int c = 0; c < 8; c++) {
        CP_WAIT2();
        __syncthreads();
        uint32_t sA = sbase + st * 32768;
        uint32_t sB = sA + 16384;
        #pragma unroll
        for (int kk = 0; kk < 4; kk++) {
            uint32_t a0[4], a1[4];
            {
                int row = wm * 32 + (lane & 15);
                int c4 = kk * 2 + (lane >> 4);
                ldsm_x4(a0, sA + (row * 8 + (c4 ^ (row & 7))) * 16);
                int row1 = row + 16;
                ldsm_x4(a1, sA + (row1 * 8 + (c4 ^ (row1 & 7))) * 16);
            }
            uint32_t b[4][4];
            #pragma unroll
            for (int p = 0; p < 4; p++) {
                int nrow = wn * 64 + p * 16 + ((lane >> 4) << 3) + (lane & 7);
                int c4 = kk * 2 + ((lane >> 3) & 1);
                ldsm_x4(b[p], sB + (nrow * 8 + (c4 ^ (nrow & 7))) * 16);
            }
            #pragma unroll
            for (int nt = 0; nt < 8; nt++) {
                mma16816(acc[0][nt], a0, &b[nt >> 1][(nt & 1) * 2]);
                mma16816(acc[1][nt], a1, &b[nt >> 1][(nt & 1) * 2]);
            }
        }
        __syncthreads();
        if (c + 3 < 8) prefetch(c + 3, st);
        CP_COMMIT();
        st = (st == 2) ? 0 : st + 1;
    }

    int r0 = tile * 128 + wm * 32 + (lane >> 2);
    int cb = wn * 64 + (lane & 3) * 2;
    #pragma unroll
    for (int mt = 0; mt < 2; mt++) {
        #pragma unroll
        for (int nt = 0; nt < 8; nt++) {
            int col = cb + nt * 8;
            int row = r0 + mt * 16;
            float bx = bias[col], by = bias[col + 1];
            __half2 v;
            v = __floats2half2_rn(fmaxf(acc[mt][nt][0] + bx, 0.f),
                                  fmaxf(acc[mt][nt][1] + by, 0.f));
            *(__half2*)&yout[(size_t)row * HD + col] = v;
            v = __floats2half2_rn(fmaxf(acc[mt][nt][2] + bx, 0.f),
                                  fmaxf(acc[mt][nt][3] + by, 0.f));
            *(__half2*)&yout[(size_t)(row + 8) * HD + col] = v;
        }
    }
}

// ---------------- mixup: fp16 y in, fp16 hi/lo of new x out ----------------
__global__ void mixup_kernel(const float* __restrict__ lam, int which,
                             const __half* __restrict__ yin) {
    int warp = (blockIdx.x * blockDim.x + threadIdx.x) >> 5;
    if (warp >= NN) return;
    int lane = threadIdx.x & 31;
    const int* perm = which ? g_p2 : g_p1;
    int p = perm[warp];
    float l = lam[0];
    uint2 pa = *(const uint2*)&yin[warp * HD + lane * 4];
    uint2 pb = *(const uint2*)&yin[p * HD + lane * 4];
    float2 a0 = __half22float2(*(const __half2*)&pa.x);
    float2 a1 = __half22float2(*(const __half2*)&pa.y);
    float2 b0 = __half22float2(*(const __half2*)&pb.x);
    float2 b1 = __half22float2(*(const __half2*)&pb.y);
    float4 o;
    o.x = l * a0.x + (1.f - l) * b0.x;
    o.y = l * a0.y + (1.f - l) * b0.y;
    o.z = l * a1.x + (1.f - l) * b1.x;
    o.w = l * a1.y + (1.f - l) * b1.y;
    write_hilo(g_xh, g_xl, warp, lane, o);
}

// ---------------- fused pool + head (segment-local; mixup3 no-op) ----------
__global__ void poolhead_kernel(const __half* __restrict__ yin,
                                const float* __restrict__ Wl,
                                const float* __restrict__ bl,
                                float* __restrict__ out) {
    __shared__ float ps[256];
    int g = blockIdx.x, t = threadIdx.x;
    int col = t & 127, half = t >> 7;
    float acc = 0.f;
    int base = g * SEG + half * 200;
    #pragma unroll 4
    for (int r = 0; r < 200; r++)
        acc += __half2float(yin[(size_t)(base + r) * HD + col]);
    ps[t] = acc;
    __syncthreads();
    if (t < 128) ps[t] += ps[t + 128];
    __syncthreads();
    if (t < 32) {
        float pv[4];
        #pragma unroll
        for (int q = 0; q < 4; q++) pv[q] = ps[t + q * 32];
        float logits[OUTC];
        #pragma unroll
        for (int o = 0; o < OUTC; o++) {
            float s = 0.f;
            #pragma unroll
            for (int q = 0; q < 4; q++)
                s += pv[q] * Wl[(t + q * 32) * OUTC + o];
            #pragma unroll
            for (int off = 16; off; off >>= 1)
                s += __shfl_down_sync(0xffffffffu, s, off);
            logits[o] = s;
        }
        if (t == 0) {
            float m = -1e30f;
            #pragma unroll
            for (int o = 0; o < OUTC; o++) {
                logits[o] += bl[o];
                m = fmaxf(m, logits[o]);
            }
            float se = 0.f;
            #pragma unroll
            for (int o = 0; o < OUTC; o++) se += expf(logits[o] - m);
            float lse = m + logf(se);
            #pragma unroll
            for (int o = 0; o < OUTC; o++) out[g * OUTC + o] = logits[o] - lse;
        }
    }
}

// ---------------- launch ----------------------------------------------------
extern "C" void kernel_launch(void* const* d_in, const int* in_sizes, int n_in,
                              void* d_out, int out_size) {
    const float* x0      = (const float*)d_in[0];
    const void*  eidx    = d_in[1];
    const float* lam     = (const float*)d_in[2];
    const void*  perm1   = d_in[5];
    const void*  perm2   = d_in[6];
    const float* W1_rel  = (const float*)d_in[8];
    const float* b1_rel  = (const float*)d_in[9];
    const float* W1_root = (const float*)d_in[10];
    const float* W2_rel  = (const float*)d_in[11];
    const float* b2_rel  = (const float*)d_in[12];
    const float* W2_root = (const float*)d_in[13];
    const float* W_lin   = (const float*)d_in[14];
    const float* b_lin   = (const float*)d_in[15];
    float* out = (float*)d_out;

    const int GEMM_SMEM = 3 * 32768;
    static int smem_set = 0;
    if (!smem_set) {
        cudaFuncSetAttribute(gemm_kernel,
                             cudaFuncAttributeMaxDynamicSharedMemorySize, GEMM_SMEM);
        smem_set = 1;
    }

    convhist_kernel<<<(NE + 255) / 256, 256>>>(eidx, perm1, perm2);
    scan1_kernel<<<(NN + 255) / 256, 256>>>();
    scan23_kernel<<<(NN + 255) / 256, 256>>>();
    scatter_kernel<<<(NE + 255) / 256, 256>>>();
    prep_kernel<<<NN / 8 + 4, 256>>>(x0, W1_root, W1_rel, W2_root, W2_rel);

    __half *xh, *xl, *ah, *al, *w, *gy;
    cudaGetSymbolAddress((void**)&xh, g_xh);
    cudaGetSymbolAddress((void**)&xl, g_xl);
    cudaGetSymbolAddress((void**)&ah, g_ah);
    cudaGetSymbolAddress((void**)&al, g_al);
    cudaGetSymbolAddress((void**)&w,  g_w);
    cudaGetSymbolAddress((void**)&gy, g_y);
    __half* w0r = w + 0 * HD * HD;
    __half* w0e = w + 1 * HD * HD;
    __half* w1r = w + 2 * HD * HD;
    __half* w1e = w + 3 * HD * HD;

    // Layer 1
    agg_kernel<<<(NN * 32 + 255) / 256, 256>>>();
    gemm_kernel<<<NT, 256, GEMM_SMEM>>>(xh, xl, ah, al, w0r, w0e, b1_rel, gy);
    mixup_kernel<<<(NN * 32 + 255) / 256, 256>>>(lam, 0, gy);

    // Layer 2
    agg_kernel<<<(NN * 32 + 255) / 256, 256>>>();
    gemm_kernel<<<NT, 256, GEMM_SMEM>>>(xh, xl, ah, al, w1r, w1e, b2_rel, gy);
    mixup_kernel<<<(NN * 32 + 255) / 256, 256>>>(lam, 1, gy);

    // Layer 3 (conv2 weights reused; mixup3 invariant under pooling)
    agg_kernel<<<(NN * 32 + 255) / 256, 256>>>();
    gemm_kernel<<<NT, 256, GEMM_SMEM>>>(xh, xl, ah, al, w1r, w1e, b2_rel, gy);

    poolhead_kernel<<<NG, 256>>>(gy, W_lin, b_lin, out);
}

// round 14
// speedup vs baseline: 1.0279x; 1.0119x over previous
#include <cuda_runtime.h>
#include <cuda_fp16.h>
#include <math.h>
#include <stdint.h>

#define NN 51200      // nodes
#define NE 819200     // edges
#define HD 128        // hidden / in dim
#define NG 128        // graphs
#define SEG 400       // nodes per graph
#define OUTC 10
#define NT  (NN / 128)          // 400 M-tiles

// ---------------- scratch (device globals) ---------------------------------
__device__ __align__(16) __half g_y[NN * HD];    // conv output (post-relu), fp16
__device__ __align__(16) __half g_xh[NN * HD];   // fp16 hi of x (also gather src)
__device__ __align__(16) __half g_xl[NN * HD];   // fp16 residual of x
__device__ __align__(16) __half g_ah[NN * HD];   // fp16 hi of agg
__device__ __align__(16) __half g_al[NN * HD];   // fp16 residual of agg
__device__ __align__(16) __half g_w[4 * HD * HD]; // weight hi images [n][k]
__device__ int   g_src[NE];
__device__ int   g_dst[NE];
__device__ int   g_rank[NE];       // within-dst-bucket rank (from hist atomic)
__device__ int   g_p1[NN];
__device__ int   g_p2[NN];
__device__ int   g_cnt[NN];        // zero at load; scan1 re-zeroes each pass
__device__ int   g_scanL[NN];
__device__ int   g_bsum[256];
__device__ int   g_rowstart[NN + 1];
__device__ int   g_eidx[NE];

// ---------------- helpers ---------------------------------------------------
__device__ __forceinline__ uint32_t smem_to_u32(const void* p) {
    uint32_t a;
    asm("{ .reg .u64 t; cvta.to.shared.u64 t, %1; cvt.u32.u64 %0, t; }"
        : "=r"(a) : "l"(p));
    return a;
}
#define CP_ASYNC16(dst, src) \
    asm volatile("cp.async.cg.shared.global [%0], [%1], 16;" \
                 :: "r"(dst), "l"(src) : "memory")
#define CP_COMMIT() asm volatile("cp.async.commit_group;" ::: "memory")
#define CP_WAIT2()  asm volatile("cp.async.wait_group 2;" ::: "memory")

__device__ __forceinline__ void ldsm_x4(uint32_t* r, uint32_t addr) {
    asm volatile("ldmatrix.sync.aligned.m8n8.x4.shared.b16 {%0,%1,%2,%3}, [%4];"
                 : "=r"(r[0]), "=r"(r[1]), "=r"(r[2]), "=r"(r[3]) : "r"(addr));
}
__device__ __forceinline__ void mma16816(float* c, const uint32_t* a, const uint32_t* b) {
    asm volatile("mma.sync.aligned.m16n8k16.row.col.f32.f16.f16.f32 "
                 "{%0,%1,%2,%3},{%4,%5,%6,%7},{%8,%9},{%0,%1,%2,%3};"
                 : "+f"(c[0]), "+f"(c[1]), "+f"(c[2]), "+f"(c[3])
                 : "r"(a[0]), "r"(a[1]), "r"(a[2]), "r"(a[3]), "r"(b[0]), "r"(b[1]));
}

__device__ __forceinline__ uint32_t pack2(__half a, __half b) {
    return (uint32_t)__half_as_ushort(a) | ((uint32_t)__half_as_ushort(b) << 16);
}

// fp16 hi/residual split: hi + lo == v to ~2^-22 relative
__device__ __forceinline__ void write_hilo(__half* hi, __half* lo,
                                           int node, int lane, float4 v) {
    int off = node * HD + lane * 4;
    __half hx = __float2half_rn(v.x), hy = __float2half_rn(v.y);
    __half hz = __float2half_rn(v.z), hw = __float2half_rn(v.w);
    uint2 ph, pl;
    ph.x = pack2(hx, hy);
    ph.y = pack2(hz, hw);
    pl.x = pack2(__float2half_rn(v.x - __half2float(hx)),
                 __float2half_rn(v.y - __half2float(hy)));
    pl.y = pack2(__float2half_rn(v.z - __half2float(hz)),
                 __float2half_rn(v.w - __half2float(hw)));
    *(uint2*)&hi[off] = ph;
    *(uint2*)&lo[off] = pl;
}

// ---------------- convert + histogram + rank (+ inline dtype detect) --------
__global__ void convhist_kernel(const void* __restrict__ eraw,
                                const void* __restrict__ p1raw,
                                const void* __restrict__ p2raw) {
    __shared__ int s_is64;
    int tid = threadIdx.x;
    if (tid == 0) {
        const unsigned* e = (const unsigned*)eraw;
        int all0 = 1;
        #pragma unroll 1
        for (int k = 0; k < 8; k++)
            if (e[2 * k + 1] != 0u) { all0 = 0; break; }
        s_is64 = all0;
    }
    __syncthreads();
    const bool is64 = (s_is64 != 0);
    int i = blockIdx.x * blockDim.x + tid;
    if (i < NE) {
        int s = is64 ? (int)((const long long*)eraw)[i] : ((const int*)eraw)[i];
        int d = is64 ? (int)((const long long*)eraw)[NE + i] : ((const int*)eraw)[NE + i];
        g_src[i] = s;
        g_dst[i] = d;
        g_rank[i] = atomicAdd(&g_cnt[d], 1);
    }
    if (i < NN) {
        g_p1[i] = is64 ? (int)((const long long*)p1raw)[i] : ((const int*)p1raw)[i];
        g_p2[i] = is64 ? (int)((const long long*)p2raw)[i] : ((const int*)p2raw)[i];
    }
}

// ---------------- scan chain: scan1 (+cnt clear), scan23 --------------------
__global__ void scan1_kernel() {
    __shared__ int sh[256];
    int b = blockIdx.x, t = threadIdx.x;
    int i = b * 256 + t;
    int v = (i < NN) ? g_cnt[i] : 0;
    if (i < NN) g_cnt[i] = 0;        // self-clean for next replay
    sh[t] = v;
    __syncthreads();
    #pragma unroll
    for (int off = 1; off < 256; off <<= 1) {
        int add = (t >= off) ? sh[t - off] : 0;
        __syncthreads();
        sh[t] += add;
        __syncthreads();
    }
    if (i < NN) g_scanL[i] = sh[t] - v;
    if (t == 255) g_bsum[b] = sh[255];
}

// per-block re-derivation of the 200-entry block-sum prefix (replaces scan2)
__global__ void scan23_kernel() {
    __shared__ int sh[256];
    int b = blockIdx.x, t = threadIdx.x;
    int v = (t < NN / 256) ? g_bsum[t] : 0;
    sh[t] = v;
    __syncthreads();
    #pragma unroll
    for (int off = 1; off < 256; off <<= 1) {
        int add = (t >= off) ? sh[t - off] : 0;
        __syncthreads();
        sh[t] += add;
        __syncthreads();
    }
    int boff = (b == 0) ? 0 : sh[b - 1];   // exclusive prefix for this block
    int i = b * 256 + t;
    if (i < NN) g_rowstart[i] = g_scanL[i] + boff;
    if (b == 0 && t == 0) g_rowstart[NN] = NE;
}

// atomic-free scatter: position = rowstart[dst] + rank (captured in convhist)
__global__ void scatter_kernel() {
    int e = blockIdx.x * blockDim.x + threadIdx.x;
    if (e < NE) {
        int pos = g_rowstart[g_dst[e]] + g_rank[e];
        g_eidx[pos] = g_src[e];
    }
}

// ---------------- merged prep: x0 fp16 split + weight images ---------------
__global__ void prep_kernel(const float* __restrict__ xin,
                            const float* __restrict__ W0r,
                            const float* __restrict__ W0e,
                            const float* __restrict__ W1r,
                            const float* __restrict__ W1e) {
    if (blockIdx.x < NN / 8) {
        int warp = (blockIdx.x * blockDim.x + threadIdx.x) >> 5;
        int lane = threadIdx.x & 31;
        float4 v = *(const float4*)&xin[(size_t)warp * HD + lane * 4];
        write_hilo(g_xh, g_xl, warp, lane, v);
    } else {
        if (threadIdx.x >= 128) return;
        int m = blockIdx.x - NN / 8;
        const float* Ws[4] = {W0r, W0e, W1r, W1e};
        const float* W = Ws[m];
        __half* hi = g_w + (size_t)m * HD * HD;
        int n = threadIdx.x;
        for (int k0 = 0; k0 < HD; k0 += 4) {
            uint2 p;
            p.x = pack2(__float2half_rn(W[(k0 + 0) * HD + n]),
                        __float2half_rn(W[(k0 + 1) * HD + n]));
            p.y = pack2(__float2half_rn(W[(k0 + 2) * HD + n]),
                        __float2half_rn(W[(k0 + 3) * HD + n]));
            *(uint2*)&hi[n * HD + k0] = p;
        }
    }
}

// ---------------- aggregation: warp/node; indices batched via shuffle ------
// Breaks the eidx->feature dependent-load chain: all <=32 indices of a chunk
// load in ONE coalesced lane-parallel load, then feature rows stream with
// MLP=4 (independent addresses from shfl broadcast).
__global__ void agg_kernel() {
    int warp = (blockIdx.x * blockDim.x + threadIdx.x) >> 5;
    if (warp >= NN) return;
    int lane = threadIdx.x & 31;
    int s = g_rowstart[warp];
    int e = g_rowstart[warp + 1];
    float4 acc = make_float4(0.f, 0.f, 0.f, 0.f);
    for (int base = s; base < e; base += 32) {
        int n = e - base;
        if (n > 32) n = 32;
        int idx = (lane < n) ? g_eidx[base + lane] : 0;
        int k = 0;
        for (; k + 3 < n; k += 4) {
            int u0 = __shfl_sync(0xffffffffu, idx, k);
            int u1 = __shfl_sync(0xffffffffu, idx, k + 1);
            int u2 = __shfl_sync(0xffffffffu, idx, k + 2);
            int u3 = __shfl_sync(0xffffffffu, idx, k + 3);
            uint2 p0 = *(const uint2*)&g_xh[u0 * HD + lane * 4];
            uint2 p1 = *(const uint2*)&g_xh[u1 * HD + lane * 4];
            uint2 p2 = *(const uint2*)&g_xh[u2 * HD + lane * 4];
            uint2 p3 = *(const uint2*)&g_xh[u3 * HD + lane * 4];
            float2 a0 = __half22float2(*(const __half2*)&p0.x);
            float2 b0 = __half22float2(*(const __half2*)&p0.y);
            float2 a1 = __half22float2(*(const __half2*)&p1.x);
            float2 b1 = __half22float2(*(const __half2*)&p1.y);
            float2 a2 = __half22float2(*(const __half2*)&p2.x);
            float2 b2 = __half22float2(*(const __half2*)&p2.y);
            float2 a3 = __half22float2(*(const __half2*)&p3.x);
            float2 b3 = __half22float2(*(const __half2*)&p3.y);
            acc.x += (a0.x + a1.x) + (a2.x + a3.x);
            acc.y += (a0.y + a1.y) + (a2.y + a3.y);
            acc.z += (b0.x + b1.x) + (b2.x + b3.x);
            acc.w += (b0.y + b1.y) + (b2.y + b3.y);
        }
        for (; k < n; k++) {
            int u = __shfl_sync(0xffffffffu, idx, k);
            uint2 p = *(const uint2*)&g_xh[u * HD + lane * 4];
            float2 a = __half22float2(*(const __half2*)&p.x);
            float2 b = __half22float2(*(const __half2*)&p.y);
            acc.x += a.x; acc.y += a.y; acc.z += b.x; acc.w += b.y;
        }
    }
    write_hilo(g_ah, g_al, warp, lane, acc);
}

// ---------------- HMMA GEMM: 4 fp16 segments, fp16 y output ----------------
__global__ void __launch_bounds__(256, 2)
gemm_kernel(const __half* __restrict__ xh, const __half* __restrict__ xl,
            const __half* __restrict__ ah, const __half* __restrict__ al,
            const __half* __restrict__ wr, const __half* __restrict__ we,
            const float* __restrict__ bias, __half* __restrict__ yout) {
    extern __shared__ char smem[];
    __shared__ const uint4* Atab[4];
    __shared__ const uint4* Btab[4];
    const int tid = threadIdx.x, lane = tid & 31, wid = tid >> 5;
    const int wm = wid >> 1, wn = wid & 1;
    const int tile = blockIdx.x;

    if (tid == 0) {
        size_t toff = (size_t)tile * 128 * HD;
        Atab[0] = (const uint4*)(xh + toff); Atab[1] = (const uint4*)(ah + toff);
        Atab[2] = (const uint4*)(xl + toff); Atab[3] = (const uint4*)(al + toff);
        Btab[0] = (const uint4*)wr; Btab[1] = (const uint4*)we;
        Btab[2] = (const uint4*)wr; Btab[3] = (const uint4*)we;
    }
    __syncthreads();
    const uint32_t sbase = smem_to_u32(smem);

    auto prefetch = [&](int cc, int st) {
        int seg = cc >> 1, ko4 = (cc & 1) << 3;
        const uint4* As = Atab[seg];
        const uint4* Bs = Btab[seg];
        uint32_t sA = sbase + st * 32768;
        uint32_t sB = sA + 16384;
        #pragma unroll
        for (int i = 0; i < 4; i++) {
            int idx = tid + 256 * i;
            int row = idx >> 3, c4 = idx & 7;
            int sw = (row * 8 + (c4 ^ (row & 7))) * 16;
            CP_ASYNC16(sA + sw, As + row * 16 + ko4 + c4);
            CP_ASYNC16(sB + sw, Bs + row * 16 + ko4 + c4);
        }
    };

    prefetch(0, 0); CP_COMMIT();
    prefetch(1, 1); CP_COMMIT();
    prefetch(2, 2); CP_COMMIT();

    float acc[2][8][4] = {};
    int st = 0;
    #pragma unroll 1
    for (int c = 0; c < 8; c++) {
        CP_WAIT2();
        __syncthreads();
        uint32_t sA = sbase + st * 32768;
        uint32_t sB = sA + 16384;
        #pragma unroll
        for (int kk = 0; kk < 4; kk++) {
            uint32_t a0[4], a1[4];
            {
                int row = wm * 32 + (lane & 15);
                int c4 = kk * 2 + (lane >> 4);
                ldsm_x4(a0, sA + (row * 8 + (c4 ^ (row & 7))) * 16);
                int row1 = row + 16;
                ldsm_x4(a1, sA + (row1 * 8 + (c4 ^ (row1 & 7))) * 16);
            }
            uint32_t b[4][4];
            #pragma unroll
            for (int p = 0; p < 4; p++) {
                int nrow = wn * 64 + p * 16 + ((lane >> 4) << 3) + (lane & 7);
                int c4 = kk * 2 + ((lane >> 3) & 1);
                ldsm_x4(b[p], sB + (nrow * 8 + (c4 ^ (nrow & 7))) * 16);
            }
            #pragma unroll
            for (int nt = 0; nt < 8; nt++) {
                mma16816(acc[0][nt], a0, &b[nt >> 1][(nt & 1) * 2]);
                mma16816(acc[1][nt], a1, &b[nt >> 1][(nt & 1) * 2]);
            }
        }
        __syncthreads();
        if (c + 3 < 8) prefetch(c + 3, st);
        CP_COMMIT();
        st = (st == 2) ? 0 : st + 1;
    }

    int r0 = tile * 128 + wm * 32 + (lane >> 2);
    int cb = wn * 64 + (lane & 3) * 2;
    #pragma unroll
    for (int mt = 0; mt < 2; mt++) {
        #pragma unroll
        for (int nt = 0; nt < 8; nt++) {
            int col = cb + nt * 8;
            int row = r0 + mt * 16;
            float bx = bias[col], by = bias[col + 1];
            __half2 v;
            v = __floats2half2_rn(fmaxf(acc[mt][nt][0] + bx, 0.f),
                                  fmaxf(acc[mt][nt][1] + by, 0.f));
            *(__half2*)&yout[(size_t)row * HD + col] = v;
            v = __floats2half2_rn(fmaxf(acc[mt][nt][2] + bx, 0.f),
                                  fmaxf(acc[mt][nt][3] + by, 0.f));
            *(__half2*)&yout[(size_t)(row + 8) * HD + col] = v;
        }
    }
}

// ---------------- mixup: fp16 y in, fp16 hi/lo of new x out ----------------
__global__ void mixup_kernel(const float* __restrict__ lam, int which,
                             const __half* __restrict__ yin) {
    int warp = (blockIdx.x * blockDim.x + threadIdx.x) >> 5;
    if (warp >= NN) return;
    int lane = threadIdx.x & 31;
    const int* perm = which ? g_p2 : g_p1;
    int p = perm[warp];
    float l = lam[0];
    uint2 pa = *(const uint2*)&yin[warp * HD + lane * 4];
    uint2 pb = *(const uint2*)&yin[p * HD + lane * 4];
    float2 a0 = __half22float2(*(const __half2*)&pa.x);
    float2 a1 = __half22float2(*(const __half2*)&pa.y);
    float2 b0 = __half22float2(*(const __half2*)&pb.x);
    float2 b1 = __half22float2(*(const __half2*)&pb.y);
    float4 o;
    o.x = l * a0.x + (1.f - l) * b0.x;
    o.y = l * a0.y + (1.f - l) * b0.y;
    o.z = l * a1.x + (1.f - l) * b1.x;
    o.w = l * a1.y + (1.f - l) * b1.y;
    write_hilo(g_xh, g_xl, warp, lane, o);
}

// ---------------- fused pool + head (segment-local; mixup3 no-op) ----------
__global__ void poolhead_kernel(const __half* __restrict__ yin,
                                const float* __restrict__ Wl,
                                const float* __restrict__ bl,
                                float* __restrict__ out) {
    __shared__ float ps[256];
    int g = blockIdx.x, t = threadIdx.x;
    int col = t & 127, half = t >> 7;
    float acc = 0.f;
    int base = g * SEG + half * 200;
    #pragma unroll 4
    for (int r = 0; r < 200; r++)
        acc += __half2float(yin[(size_t)(base + r) * HD + col]);
    ps[t] = acc;
    __syncthreads();
    if (t < 128) ps[t] += ps[t + 128];
    __syncthreads();
    if (t < 32) {
        float pv[4];
        #pragma unroll
        for (int q = 0; q < 4; q++) pv[q] = ps[t + q * 32];
        float logits[OUTC];
        #pragma unroll
        for (int o = 0; o < OUTC; o++) {
            float s = 0.f;
            #pragma unroll
            for (int q = 0; q < 4; q++)
                s += pv[q] * Wl[(t + q * 32) * OUTC + o];
            #pragma unroll
            for (int off = 16; off; off >>= 1)
                s += __shfl_down_sync(0xffffffffu, s, off);
            logits[o] = s;
        }
        if (t == 0) {
            float m = -1e30f;
            #pragma unroll
            for (int o = 0; o < OUTC; o++) {
                logits[o] += bl[o];
                m = fmaxf(m, logits[o]);
            }
            float se = 0.f;
            #pragma unroll
            for (int o = 0; o < OUTC; o++) se += expf(logits[o] - m);
            float lse = m + logf(se);
            #pragma unroll
            for (int o = 0; o < OUTC; o++) out[g * OUTC + o] = logits[o] - lse;
        }
    }
}

// ---------------- launch ----------------------------------------------------
extern "C" void kernel_launch(void* const* d_in, const int* in_sizes, int n_in,
                              void* d_out, int out_size) {
    const float* x0      = (const float*)d_in[0];
    const void*  eidx    = d_in[1];
    const float* lam     = (const float*)d_in[2];
    const void*  perm1   = d_in[5];
    const void*  perm2   = d_in[6];
    const float* W1_rel  = (const float*)d_in[8];
    const float* b1_rel  = (const float*)d_in[9];
    const float* W1_root = (const float*)d_in[10];
    const float* W2_rel  = (const float*)d_in[11];
    const float* b2_rel  = (const float*)d_in[12];
    const float* W2_root = (const float*)d_in[13];
    const float* W_lin   = (const float*)d_in[14];
    const float* b_lin   = (const float*)d_in[15];
    float* out = (float*)d_out;

    const int GEMM_SMEM = 3 * 32768;
    static int smem_set = 0;
    if (!smem_set) {
        cudaFuncSetAttribute(gemm_kernel,
                             cudaFuncAttributeMaxDynamicSharedMemorySize, GEMM_SMEM);
        smem_set = 1;
    }

    convhist_kernel<<<(NE + 255) / 256, 256>>>(eidx, perm1, perm2);
    scan1_kernel<<<(NN + 255) / 256, 256>>>();
    scan23_kernel<<<(NN + 255) / 256, 256>>>();
    scatter_kernel<<<(NE + 255) / 256, 256>>>();
    prep_kernel<<<NN / 8 + 4, 256>>>(x0, W1_root, W1_rel, W2_root, W2_rel);

    __half *xh, *xl, *ah, *al, *w, *gy;
    cudaGetSymbolAddress((void**)&xh, g_xh);
    cudaGetSymbolAddress((void**)&xl, g_xl);
    cudaGetSymbolAddress((void**)&ah, g_ah);
    cudaGetSymbolAddress((void**)&al, g_al);
    cudaGetSymbolAddress((void**)&w,  g_w);
    cudaGetSymbolAddress((void**)&gy, g_y);
    __half* w0r = w + 0 * HD * HD;
    __half* w0e = w + 1 * HD * HD;
    __half* w1r = w + 2 * HD * HD;
    __half* w1e = w + 3 * HD * HD;

    // Layer 1
    agg_kernel<<<(NN * 32 + 255) / 256, 256>>>();
    gemm_kernel<<<NT, 256, GEMM_SMEM>>>(xh, xl, ah, al, w0r, w0e, b1_rel, gy);
    mixup_kernel<<<(NN * 32 + 255) / 256, 256>>>(lam, 0, gy);

    // Layer 2
    agg_kernel<<<(NN * 32 + 255) / 256, 256>>>();
    gemm_kernel<<<NT, 256, GEMM_SMEM>>>(xh, xl, ah, al, w1r, w1e, b2_rel, gy);
    mixup_kernel<<<(NN * 32 + 255) / 256, 256>>>(lam, 1, gy);

    // Layer 3 (conv2 weights reused; mixup3 invariant under pooling)
    agg_kernel<<<(NN * 32 + 255) / 256, 256>>>();
    gemm_kernel<<<NT, 256, GEMM_SMEM>>>(xh, xl, ah, al, w1r, w1e, b2_rel, gy);

    poolhead_kernel<<<NG, 256>>>(gy, W_lin, b_lin, out);
}